// round 13
// baseline (speedup 1.0000x reference)
#include <cuda_runtime.h>
#include <cstdint>

#define B_    16
#define N_    22
#define E_    8
#define TW_   59
#define MTOT_ 944
#define FIN_  1280
#define NB_RED 96
#define NE_   176
#define K8_   160
#define MT_   8
#define CS_   8            // k8-steps per smem chunk
#define NCH_  (K8_ / CS_)  // 20 chunks

__device__ float g_err[MTOT_ * N_ * E_];
__device__ float g_part[NB_RED];

// fragment-major scratch
__device__ float g_F[(size_t)MT_ * N_ * K8_ * 1024];   // [mt][n][s][mb 8][lane 32][4]
__device__ float g_W1F[(size_t)NE_ * K8_ * 512];       // [ne][s][nb 8][lane 32][2]
__device__ float g_W2F[NE_ * 8 * 512];
__device__ float g_W3F[NE_ * 8 * 512];

__device__ __forceinline__ uint32_t tf32b(float f) {
    uint32_t u;
    asm("cvt.rna.tf32.f32 %0, %1;" : "=r"(u) : "f"(f));
    return u;
}
__device__ __forceinline__ float tf32f(float f) { return __uint_as_float(tf32b(f)); }

__device__ __forceinline__ void mma_tf32(float* c, uint32_t a0, uint32_t a1, uint32_t a2, uint32_t a3,
                                         uint32_t b0, uint32_t b1) {
    asm volatile(
        "mma.sync.aligned.m16n8k8.row.col.f32.tf32.tf32.f32 "
        "{%0,%1,%2,%3}, {%4,%5,%6,%7}, {%8,%9}, {%0,%1,%2,%3};"
        : "+f"(c[0]), "+f"(c[1]), "+f"(c[2]), "+f"(c[3])
        : "r"(a0), "r"(a1), "r"(a2), "r"(a3), "r"(b0), "r"(b1));
}

__device__ __forceinline__ uint32_t smem_u32(const void* p) {
    uint32_t a;
    asm("{ .reg .u64 t; cvta.to.shared.u64 t, %1; cvt.u32.u64 %0, t; }" : "=r"(a) : "l"(p));
    return a;
}
__device__ __forceinline__ void cp16(uint32_t dst, const void* src) {
    asm volatile("cp.async.cg.shared.global [%0], [%1], 16;" :: "r"(dst), "l"(src));
}
#define CP_COMMIT() asm volatile("cp.async.commit_group;" ::: "memory")
#define CP_WAIT1()  asm volatile("cp.async.wait_group 1;" ::: "memory")
#define CP_WAIT0()  asm volatile("cp.async.wait_group 0;" ::: "memory")

// ---------------- prep 1: materialize f in fragment-major layout ----------------
__global__ __launch_bounds__(256) void fgen(const float* __restrict__ x, const int* __restrict__ nb)
{
    size_t idx = (size_t)blockIdx.x * 256 + threadIdx.x;      // float4 index
    int lane = (int)(idx & 31);
    size_t r = idx >> 5;
    int mb = (int)(r & 7); r >>= 3;
    int s  = (int)(r % K8_); r /= K8_;
    int n  = (int)(r % N_);
    int mt = (int)(r / N_);
    if (mt >= MT_) return;
    const int lr = lane >> 2, lc = lane & 3;

    int m0 = mt * 128 + mb * 16 + lr;
    int m1 = m0 + 8;
    if (m0 >= MTOT_) m0 = MTOT_ - 1;
    if (m1 >= MTOT_) m1 = MTOT_ - 1;
    int b0 = m0 / TW_, t0 = m0 - b0 * TW_;
    int b1 = m1 / TW_, t1 = m1 - b1 * TW_;
    int xb0 = (b0 * 64 + t0) * (N_ * 64);
    int xb1 = (b1 * 64 + t1) * (N_ * 64);

    int k = s * 8 + lc;
    int dt = k >> 8, rem = k & 255;
    int nbn = nb[n * 4 + (rem >> 6)];
    int koff = (dt * N_ + nbn) * 64 + (rem & 63);

    float4 v;
    v.x = tf32f(x[xb0 + koff]);
    v.y = tf32f(x[xb1 + koff]);
    v.z = tf32f(x[xb0 + koff + 4]);
    v.w = tf32f(x[xb1 + koff + 4]);
    *(float4*)&g_F[idx * 4] = v;
}

// ---------------- prep 2: W1/W2/W3 -> fragment-major ----------------
#define CNT1 (NE_ * K8_ * 256)
#define CNT2 (NE_ * 8 * 256)
__global__ __launch_bounds__(256) void wtrans(const float* __restrict__ W1,
                                              const float* __restrict__ W2,
                                              const float* __restrict__ W3)
{
    size_t idx = (size_t)blockIdx.x * 256 + threadIdx.x;      // float2 index
    if (idx < (size_t)CNT1) {
        int lane = (int)(idx & 31);
        size_t r = idx >> 5;
        int nbk = (int)(r & 7); r >>= 3;
        int s = (int)(r % K8_);
        int ne = (int)(r / K8_);
        int k = s * 8 + (lane & 3);
        int h = nbk * 8 + (lane >> 2);
        const float* src = W1 + ((size_t)ne * FIN_ + k) * 64 + h;
        g_W1F[idx * 2]     = tf32f(src[0]);
        g_W1F[idx * 2 + 1] = tf32f(src[256]);
        return;
    }
    idx -= CNT1;
    if (idx < (size_t)(2 * CNT2)) {
        int which = (int)(idx / CNT2);
        size_t id2 = idx % CNT2;
        int lane = (int)(id2 & 31);
        size_t r = id2 >> 5;
        int nbk = (int)(r & 7); r >>= 3;
        int s = (int)(r % 8);
        int ne = (int)(r / 8);
        int k = s * 8 + (lane & 3);
        int h = nbk * 8 + (lane >> 2);
        const float* W = which ? W3 : W2;
        float* Wf = which ? g_W3F : g_W2F;
        const float* src = W + ((size_t)ne * 64 + k) * 64 + h;
        Wf[id2 * 2]     = tf32f(src[0]);
        Wf[id2 * 2 + 1] = tf32f(src[256]);
    }
}

// ---------------- main: 3-layer MLP + err ----------------
// dynamic smem (floats): Abuf 2 x CS_*1024 @ 0, 8192 ; h frags @ 16384 (8192) ; errbuf overlays h
#define SM_H   16384
#define SM_ERR 16384
#define SMEM_FLOATS 24576

__global__ __launch_bounds__(256, 2) void moe_main(
    const float* __restrict__ x,
    const float* __restrict__ b1, const float* __restrict__ b2, const float* __restrict__ b3)
{
    extern __shared__ float sm[];
    const int tid = threadIdx.x, lane = tid & 31, wid = tid >> 5;
    const int wm = wid >> 2, wn = wid & 3, lr = lane >> 2, lc = lane & 3;
    const int ne = blockIdx.x;
    const int n = ne >> 3, e = ne & 7;
    const int mt = blockIdx.y;
    const int mBase = mt * 128;

    float C[4][2][4];
    auto zeroC = [&]() {
        #pragma unroll
        for (int i = 0; i < 4; ++i)
            #pragma unroll
            for (int j = 0; j < 2; ++j)
                #pragma unroll
                for (int q = 0; q < 4; ++q) C[i][j][q] = 0.f;
    };
    auto MMA8 = [&](float4 a[4], float2 b[2]) {
        uint32_t b00 = __float_as_uint(b[0].x), b01 = __float_as_uint(b[0].y);
        uint32_t b10 = __float_as_uint(b[1].x), b11 = __float_as_uint(b[1].y);
        #pragma unroll
        for (int i = 0; i < 4; ++i) {
            mma_tf32(C[i][0], __float_as_uint(a[i].x), __float_as_uint(a[i].y),
                              __float_as_uint(a[i].z), __float_as_uint(a[i].w), b00, b01);
            mma_tf32(C[i][1], __float_as_uint(a[i].x), __float_as_uint(a[i].y),
                              __float_as_uint(a[i].z), __float_as_uint(a[i].w), b10, b11);
        }
    };

    // ---------- Layer 1: A staged via cp.async double-buffer, B direct ----------
    zeroC();
    {
        const float* fAg = g_F + ((size_t)(mt * N_ + n)) * (K8_ * 1024);
        const float* fB  = g_W1F + (size_t)ne * (K8_ * 512) + (wn * 2) * 64 + lane * 2;
        const uint32_t smA = smem_u32(sm);

        // one chunk = CS_*1024 = 8192 floats; 256 threads x 16B = 1024 floats/iter -> CS_ iters
        auto issue_copy = [&](int chunk, int buf) {
            const float* src = fAg + (size_t)chunk * (CS_ * 1024) + tid * 4;
            uint32_t dst = smA + (uint32_t)(buf * (CS_ * 1024) + tid * 4) * 4u;
            #pragma unroll
            for (int i = 0; i < CS_; ++i)
                cp16(dst + i * 4096, src + i * 1024);
        };

        issue_copy(0, 0);
        CP_COMMIT();

        float2 c0[2], c1[2];
        // prefetch B for global step 0
        c0[0] = *(const float2*)(fB);
        c0[1] = *(const float2*)(fB + 64);

        for (int c = 0; c < NCH_; ++c) {
            const int buf = c & 1;
            if (c + 1 < NCH_) {
                issue_copy(c + 1, buf ^ 1);
                CP_COMMIT();
                CP_WAIT1();
            } else {
                CP_WAIT0();
            }
            __syncthreads();
            const float* As = sm + buf * (CS_ * 1024) + (wm * 4) * 128 + lane * 4;
            #pragma unroll
            for (int s = 0; s < CS_; ++s) {
                const int gs = c * CS_ + s;
                // prefetch next B
                if (gs + 1 < K8_) {
                    const float* pb = fB + (size_t)(gs + 1) * 512;
                    c1[0] = *(const float2*)(pb);
                    c1[1] = *(const float2*)(pb + 64);
                }
                float4 a[4];
                const float* pa = As + s * 1024;
                #pragma unroll
                for (int i = 0; i < 4; ++i) a[i] = *(const float4*)(pa + i * 128);
                MMA8(a, c0);
                c0[0] = c1[0]; c0[1] = c1[1];
            }
            __syncthreads();   // all reads of buf done before next copy overwrites it
        }
    }

    // write h fragments (bias+relu+tf32) into smem
    auto write_h = [&](const float* bp) {
        #pragma unroll
        for (int i = 0; i < 4; ++i)
            #pragma unroll
            for (int nf = 0; nf < 2; ++nf)
                #pragma unroll
                for (int q = 0; q < 4; ++q) {
                    int ncol = wn * 16 + nf * 8 + 2 * lc + (q & 1);
                    float v = tf32f(fmaxf(C[i][nf][q] + bp[ncol], 0.f));
                    int addr = SM_H + (wn * 2 + nf) * 1024 + (wm * 4 + i) * 128
                             + (lr * 4 + 2 * (lc & 1) + (q & 1)) * 4
                             + ((q >> 1) & 1) + 2 * (lc >> 1);
                    sm[addr] = v;
                }
    };
    auto gemm_sm = [&](const float* WF) {
        zeroC();
        const float* fb = WF + (wn * 2) * 64 + lane * 2;
        #pragma unroll
        for (int s = 0; s < 8; ++s) {
            float4 a[4];
            float2 b[2];
            const float* pa = sm + SM_H + s * 1024 + (wm * 4) * 128 + lane * 4;
            #pragma unroll
            for (int i = 0; i < 4; ++i) a[i] = *(const float4*)(pa + i * 128);
            b[0] = *(const float2*)(fb + s * 512);
            b[1] = *(const float2*)(fb + s * 512 + 64);
            MMA8(a, b);
        }
    };

    // ---------- Layer 2 ----------
    write_h(b1 + ne * 64);
    __syncthreads();
    gemm_sm(g_W2F + (size_t)ne * 4096);
    __syncthreads();

    // ---------- Layer 3 ----------
    write_h(b2 + ne * 64);
    __syncthreads();
    gemm_sm(g_W3F + (size_t)ne * 4096);
    __syncthreads();

    // ---------- epilogue: err = mean_d (pred - y)^2 ----------
    {
        float* errbuf = sm + SM_ERR;   // [128][4]
        errbuf[tid] = 0.f;
        errbuf[tid + 256] = 0.f;
        __syncthreads();

        const float* b3p = b3 + ne * 64;
        #pragma unroll
        for (int i = 0; i < 4; ++i) {
            #pragma unroll
            for (int half = 0; half < 2; ++half) {
                const int rloc = wm * 64 + i * 16 + lr + half * 8;
                const int mg = mBase + rloc;
                float s_ = 0.f;
                if (mg < MTOT_) {
                    int bb = mg / TW_, tt = mg - bb * TW_;
                    const float* y = x + ((size_t)(bb * 64 + tt + 2) * N_ + n) * 64;
                    #pragma unroll
                    for (int nf = 0; nf < 2; ++nf) {
                        const int col = wn * 16 + nf * 8 + 2 * lc;
                        float p0 = C[i][nf][half * 2 + 0] + b3p[col];
                        float p1 = C[i][nf][half * 2 + 1] + b3p[col + 1];
                        float d0 = p0 - y[col];
                        float d1 = p1 - y[col + 1];
                        s_ += d0 * d0 + d1 * d1;
                    }
                }
                s_ += __shfl_xor_sync(0xffffffffu, s_, 1);
                s_ += __shfl_xor_sync(0xffffffffu, s_, 2);
                if (lc == 0) errbuf[rloc * 4 + wn] = s_;
            }
        }
        __syncthreads();
        if (tid < 128) {
            int mg = mBase + tid;
            if (mg < MTOT_) {
                float s_ = errbuf[tid * 4] + errbuf[tid * 4 + 1] + errbuf[tid * 4 + 2] + errbuf[tid * 4 + 3];
                g_err[(mg * N_ + n) * E_ + e] = s_ * (1.f / 64.f);
            }
        }
    }
}

// ---------------- reduction stage 1 ----------------
__global__ __launch_bounds__(256) void moe_red_part()
{
    __shared__ float red[256];
    const int tid = threadIdx.x;
    const int r = blockIdx.x * 256 + tid;
    float local = 0.f;
    if (r < MTOT_ * N_) {
        const float* ep = g_err + r * E_;
        float v[8];
        #pragma unroll
        for (int i = 0; i < 8; ++i) v[i] = ep[i];
        float mn = v[0];
        #pragma unroll
        for (int i = 1; i < 8; ++i) mn = fminf(mn, v[i]);
        float ex[8]; float Z = 0.f;
        #pragma unroll
        for (int i = 0; i < 8; ++i) { ex[i] = expf(mn - v[i]); Z += ex[i]; }
        float inv = 1.f / Z;
        float kl = 0.f;
        #pragma unroll
        for (int i = 0; i < 8; ++i) {
            float p = ex[i] * inv;
            kl += p * (logf(p + 1e-9f) + 2.0794415416798357f);
        }
        local = mn + 0.01f * kl;
    }
    red[tid] = local;
    __syncthreads();
    for (int s = 128; s > 0; s >>= 1) {
        if (tid < s) red[tid] += red[tid + s];
        __syncthreads();
    }
    if (tid == 0) g_part[blockIdx.x] = red[0];
}

// ---------------- reduction stage 2 ----------------
__global__ __launch_bounds__(128) void moe_red_final(float* __restrict__ out)
{
    __shared__ float red[128];
    const int tid = threadIdx.x;
    red[tid] = (tid < NB_RED) ? g_part[tid] : 0.f;
    __syncthreads();
    for (int s = 64; s > 0; s >>= 1) {
        if (tid < s) red[tid] += red[tid + s];
        __syncthreads();
    }
    if (tid == 0) out[0] = red[0] * (1.0f / 20160.0f);
    if (tid < B_) {
        int m = tid * TW_ + (TW_ - 1);
        const float* ep = g_err + (m * N_ + (N_ - 1)) * E_;
        float best = ep[0]; int bi = 0;
        #pragma unroll
        for (int i = 1; i < 8; ++i) {
            float vv = ep[i];
            if (vv < best) { best = vv; bi = i; }
        }
        out[1 + tid] = (float)bi;
    }
}

extern "C" void kernel_launch(void* const* d_in, const int* in_sizes, int n_in,
                              void* d_out, int out_size)
{
    const float* x  = (const float*)d_in[0];
    const int*   nb = (const int*)d_in[1];
    const float* W1 = (const float*)d_in[2];
    const float* b1 = (const float*)d_in[3];
    const float* W2 = (const float*)d_in[4];
    const float* b2 = (const float*)d_in[5];
    const float* W3 = (const float*)d_in[6];
    const float* b3 = (const float*)d_in[7];
    float* out = (float*)d_out;

    fgen<<<28160, 256>>>(x, nb);
    wtrans<<<30976, 256>>>(W1, W2, W3);

    size_t smem = SMEM_FLOATS * sizeof(float);
    cudaFuncSetAttribute(moe_main, cudaFuncAttributeMaxDynamicSharedMemorySize, (int)smem);
    moe_main<<<dim3(NE_, MT_), 256, smem>>>(x, b1, b2, b3);

    moe_red_part<<<NB_RED, 256>>>();
    moe_red_final<<<1, 128>>>(out);
}

// round 17
// speedup vs baseline: 1.2040x; 1.2040x over previous
#include <cuda_runtime.h>
#include <cstdint>

#define B_    16
#define N_    22
#define E_    8
#define TW_   59
#define MTOT_ 944
#define FIN_  1280
#define NB_RED 96
#define NE_   176
#define K8_   160
#define MT_   8

__device__ float g_err[MTOT_ * N_ * E_];
__device__ float g_part[NB_RED];

// fragment-major scratch
__device__ float g_F[(size_t)MT_ * N_ * K8_ * 1024];   // [mt][n][s][mb 8][lane 32][4]
__device__ float g_W1F[(size_t)NE_ * K8_ * 512];       // [ne][s][nb 8][lane 32][2]
__device__ float g_W2F[NE_ * 8 * 512];
__device__ float g_W3F[NE_ * 8 * 512];

__device__ __forceinline__ uint32_t tf32b(float f) {
    uint32_t u;
    asm("cvt.rna.tf32.f32 %0, %1;" : "=r"(u) : "f"(f));
    return u;
}
__device__ __forceinline__ float tf32f(float f) { return __uint_as_float(tf32b(f)); }

__device__ __forceinline__ void mma_tf32(float* c, uint32_t a0, uint32_t a1, uint32_t a2, uint32_t a3,
                                         uint32_t b0, uint32_t b1) {
    asm volatile(
        "mma.sync.aligned.m16n8k8.row.col.f32.tf32.tf32.f32 "
        "{%0,%1,%2,%3}, {%4,%5,%6,%7}, {%8,%9}, {%0,%1,%2,%3};"
        : "+f"(c[0]), "+f"(c[1]), "+f"(c[2]), "+f"(c[3])
        : "r"(a0), "r"(a1), "r"(a2), "r"(a3), "r"(b0), "r"(b1));
}

// ---------------- prep 1: materialize f in fragment-major layout ----------------
__global__ __launch_bounds__(256) void fgen(const float* __restrict__ x, const int* __restrict__ nb)
{
    size_t idx = (size_t)blockIdx.x * 256 + threadIdx.x;      // float4 index
    int lane = (int)(idx & 31);
    size_t r = idx >> 5;
    int mb = (int)(r & 7); r >>= 3;
    int s  = (int)(r % K8_); r /= K8_;
    int n  = (int)(r % N_);
    int mt = (int)(r / N_);
    if (mt >= MT_) return;
    const int lr = lane >> 2, lc = lane & 3;

    int m0 = mt * 128 + mb * 16 + lr;
    int m1 = m0 + 8;
    if (m0 >= MTOT_) m0 = MTOT_ - 1;
    if (m1 >= MTOT_) m1 = MTOT_ - 1;
    int b0 = m0 / TW_, t0 = m0 - b0 * TW_;
    int b1 = m1 / TW_, t1 = m1 - b1 * TW_;
    int xb0 = (b0 * 64 + t0) * (N_ * 64);
    int xb1 = (b1 * 64 + t1) * (N_ * 64);

    int k = s * 8 + lc;
    int dt = k >> 8, rem = k & 255;
    int nbn = nb[n * 4 + (rem >> 6)];
    int koff = (dt * N_ + nbn) * 64 + (rem & 63);

    float4 v;
    v.x = tf32f(x[xb0 + koff]);
    v.y = tf32f(x[xb1 + koff]);
    v.z = tf32f(x[xb0 + koff + 4]);
    v.w = tf32f(x[xb1 + koff + 4]);
    *(float4*)&g_F[idx * 4] = v;
}

// ---------------- prep 2: W1/W2/W3 -> fragment-major ----------------
#define CNT1 (NE_ * K8_ * 256)
#define CNT2 (NE_ * 8 * 256)
__global__ __launch_bounds__(256) void wtrans(const float* __restrict__ W1,
                                              const float* __restrict__ W2,
                                              const float* __restrict__ W3)
{
    size_t idx = (size_t)blockIdx.x * 256 + threadIdx.x;      // float2 index
    if (idx < (size_t)CNT1) {
        int lane = (int)(idx & 31);
        size_t r = idx >> 5;
        int nbk = (int)(r & 7); r >>= 3;
        int s = (int)(r % K8_);
        int ne = (int)(r / K8_);
        int k = s * 8 + (lane & 3);
        int h = nbk * 8 + (lane >> 2);
        const float* src = W1 + ((size_t)ne * FIN_ + k) * 64 + h;
        g_W1F[idx * 2]     = tf32f(src[0]);
        g_W1F[idx * 2 + 1] = tf32f(src[256]);
        return;
    }
    idx -= CNT1;
    if (idx < (size_t)(2 * CNT2)) {
        int which = (int)(idx / CNT2);
        size_t id2 = idx % CNT2;
        int lane = (int)(id2 & 31);
        size_t r = id2 >> 5;
        int nbk = (int)(r & 7); r >>= 3;
        int s = (int)(r % 8);
        int ne = (int)(r / 8);
        int k = s * 8 + (lane & 3);
        int h = nbk * 8 + (lane >> 2);
        const float* W = which ? W3 : W2;
        float* Wf = which ? g_W3F : g_W2F;
        const float* src = W + ((size_t)ne * 64 + k) * 64 + h;
        Wf[id2 * 2]     = tf32f(src[0]);
        Wf[id2 * 2 + 1] = tf32f(src[256]);
    }
}

// ---------------- main: 3-layer MLP + err, 2 experts per CTA ----------------
// dynamic smem (floats): h fragment regions, one per expert: 2 x 8192 @ 0; errbuf overlays after layer 3
#define SMEM_FLOATS 16384

__global__ __launch_bounds__(256, 2) void moe_main(
    const float* __restrict__ x,
    const float* __restrict__ b1, const float* __restrict__ b2, const float* __restrict__ b3)
{
    extern __shared__ float sm[];
    const int tid = threadIdx.x, lane = tid & 31, wid = tid >> 5;
    const int wm = wid >> 2, wn = wid & 3, lr = lane >> 2, lc = lane & 3;
    const int pg = blockIdx.x;            // 0..87
    const int n = pg >> 2;
    const int e0 = (pg & 3) * 2;
    const int ew = e0 + (wn >> 1);        // this warp's expert
    const int ne_w = n * 8 + ew;
    const int nb0 = (wn & 1) * 4;         // first of 4 nb-blocks this warp owns
    const int mt = blockIdx.y;
    const int mBase = mt * 128;
    const int hreg = (wn >> 1) * 8192;    // smem h region for this warp's expert

    float C[4][4][4];
    auto zeroC = [&]() {
        #pragma unroll
        for (int i = 0; i < 4; ++i)
            #pragma unroll
            for (int j = 0; j < 4; ++j)
                #pragma unroll
                for (int q = 0; q < 4; ++q) C[i][j][q] = 0.f;
    };
    auto MMA16 = [&](float4 a[4], float2 b[4]) {
        #pragma unroll
        for (int j = 0; j < 4; ++j) {
            uint32_t b0 = __float_as_uint(b[j].x), b1 = __float_as_uint(b[j].y);
            #pragma unroll
            for (int i = 0; i < 4; ++i)
                mma_tf32(C[i][j], __float_as_uint(a[i].x), __float_as_uint(a[i].y),
                                  __float_as_uint(a[i].z), __float_as_uint(a[i].w), b0, b1);
        }
    };

    // ---------- Layer 1: direct-from-gmem fragments ----------
    zeroC();
    {
        const float* fA = g_F + ((size_t)(mt * N_ + n)) * (K8_ * 1024) + (wm * 4) * 128 + lane * 4;
        const float* fB = g_W1F + (size_t)ne_w * (K8_ * 512) + nb0 * 64 + lane * 2;
        float2 cb0[4], cb1[4];
        #pragma unroll
        for (int j = 0; j < 4; ++j) cb0[j] = *(const float2*)(fB + j * 64);

        for (int s = 0; s < K8_; ++s) {
            if (s + 1 < K8_) {
                const float* pb = fB + (size_t)(s + 1) * 512;
                #pragma unroll
                for (int j = 0; j < 4; ++j) cb1[j] = *(const float2*)(pb + j * 64);
            }
            float4 a[4];
            const float* pa = fA + (size_t)s * 1024;
            #pragma unroll
            for (int i = 0; i < 4; ++i) a[i] = *(const float4*)(pa + i * 128);
            MMA16(a, cb0);
            #pragma unroll
            for (int j = 0; j < 4; ++j) cb0[j] = cb1[j];
        }
    }

    // write h fragments (bias+relu+tf32) into this expert's smem region
    auto write_h = [&](const float* bfull) {
        const float* bp = bfull + ne_w * 64;
        #pragma unroll
        for (int i = 0; i < 4; ++i)
            #pragma unroll
            for (int nf = 0; nf < 4; ++nf)
                #pragma unroll
                for (int q = 0; q < 4; ++q) {
                    int ncol = (nb0 + nf) * 8 + 2 * lc + (q & 1);
                    float v = tf32f(fmaxf(C[i][nf][q] + bp[ncol], 0.f));
                    int addr = hreg + (nb0 + nf) * 1024 + (wm * 4 + i) * 128
                             + (lr * 4 + 2 * (lc & 1) + (q & 1)) * 4
                             + ((q >> 1) & 1) + 2 * (lc >> 1);
                    sm[addr] = v;
                }
    };
    auto gemm_sm = [&](const float* WFbase) {
        zeroC();
        const float* fb = WFbase + (size_t)ne_w * 4096 + nb0 * 64 + lane * 2;
        #pragma unroll
        for (int s = 0; s < 8; ++s) {
            float4 a[4];
            float2 b[4];
            const float* pa = sm + hreg + s * 1024 + (wm * 4) * 128 + lane * 4;
            #pragma unroll
            for (int i = 0; i < 4; ++i) a[i] = *(const float4*)(pa + i * 128);
            #pragma unroll
            for (int j = 0; j < 4; ++j) b[j] = *(const float2*)(fb + s * 512 + j * 64);
            MMA16(a, b);
        }
    };

    // ---------- Layer 2 ----------
    write_h(b1);
    __syncthreads();
    gemm_sm(g_W2F);
    __syncthreads();

    // ---------- Layer 3 ----------
    write_h(b2);
    __syncthreads();
    gemm_sm(g_W3F);
    __syncthreads();

    // ---------- epilogue: err = mean_d (pred - y)^2, both experts ----------
    {
        float* errbuf = sm;          // [128][4]
        errbuf[tid] = 0.f;
        errbuf[tid + 256] = 0.f;
        __syncthreads();

        const float* b3p = b3 + ne_w * 64;
        #pragma unroll
        for (int i = 0; i < 4; ++i) {
            #pragma unroll
            for (int half = 0; half < 2; ++half) {
                const int rloc = wm * 64 + i * 16 + lr + half * 8;
                const int mg = mBase + rloc;
                float s_ = 0.f;
                if (mg < MTOT_) {
                    int bb = mg / TW_, tt = mg - bb * TW_;
                    const float* y = x + ((size_t)(bb * 64 + tt + 2) * N_ + n) * 64;
                    #pragma unroll
                    for (int nf = 0; nf < 4; ++nf) {
                        const int col = (nb0 + nf) * 8 + 2 * lc;
                        float p0 = C[i][nf][half * 2 + 0] + b3p[col];
                        float p1 = C[i][nf][half * 2 + 1] + b3p[col + 1];
                        float d0 = p0 - y[col];
                        float d1 = p1 - y[col + 1];
                        s_ += d0 * d0 + d1 * d1;
                    }
                }
                s_ += __shfl_xor_sync(0xffffffffu, s_, 1);
                s_ += __shfl_xor_sync(0xffffffffu, s_, 2);
                if (lc == 0) errbuf[rloc * 4 + wn] = s_;
            }
        }
        __syncthreads();
        if (tid < 128) {
            int mg = mBase + tid;
            if (mg < MTOT_) {
                float s0 = errbuf[tid * 4 + 0] + errbuf[tid * 4 + 1];
                float s1 = errbuf[tid * 4 + 2] + errbuf[tid * 4 + 3];
                g_err[(mg * N_ + n) * E_ + e0]     = s0 * (1.f / 64.f);
                g_err[(mg * N_ + n) * E_ + e0 + 1] = s1 * (1.f / 64.f);
            }
        }
    }
}

// ---------------- reduction stage 1 ----------------
__global__ __launch_bounds__(256) void moe_red_part()
{
    __shared__ float red[256];
    const int tid = threadIdx.x;
    const int r = blockIdx.x * 256 + tid;
    float local = 0.f;
    if (r < MTOT_ * N_) {
        const float* ep = g_err + r * E_;
        float v[8];
        #pragma unroll
        for (int i = 0; i < 8; ++i) v[i] = ep[i];
        float mn = v[0];
        #pragma unroll
        for (int i = 1; i < 8; ++i) mn = fminf(mn, v[i]);
        float ex[8]; float Z = 0.f;
        #pragma unroll
        for (int i = 0; i < 8; ++i) { ex[i] = expf(mn - v[i]); Z += ex[i]; }
        float inv = 1.f / Z;
        float kl = 0.f;
        #pragma unroll
        for (int i = 0; i < 8; ++i) {
            float p = ex[i] * inv;
            kl += p * (logf(p + 1e-9f) + 2.0794415416798357f);
        }
        local = mn + 0.01f * kl;
    }
    red[tid] = local;
    __syncthreads();
    for (int s = 128; s > 0; s >>= 1) {
        if (tid < s) red[tid] += red[tid + s];
        __syncthreads();
    }
    if (tid == 0) g_part[blockIdx.x] = red[0];
}

// ---------------- reduction stage 2 ----------------
__global__ __launch_bounds__(128) void moe_red_final(float* __restrict__ out)
{
    __shared__ float red[128];
    const int tid = threadIdx.x;
    red[tid] = (tid < NB_RED) ? g_part[tid] : 0.f;
    __syncthreads();
    for (int s = 64; s > 0; s >>= 1) {
        if (tid < s) red[tid] += red[tid + s];
        __syncthreads();
    }
    if (tid == 0) out[0] = red[0] * (1.0f / 20160.0f);
    if (tid < B_) {
        int m = tid * TW_ + (TW_ - 1);
        const float* ep = g_err + (m * N_ + (N_ - 1)) * E_;
        float best = ep[0]; int bi = 0;
        #pragma unroll
        for (int i = 1; i < 8; ++i) {
            float vv = ep[i];
            if (vv < best) { best = vv; bi = i; }
        }
        out[1 + tid] = (float)bi;
    }
}

extern "C" void kernel_launch(void* const* d_in, const int* in_sizes, int n_in,
                              void* d_out, int out_size)
{
    const float* x  = (const float*)d_in[0];
    const int*   nb = (const int*)d_in[1];
    const float* W1 = (const float*)d_in[2];
    const float* b1 = (const float*)d_in[3];
    const float* W2 = (const float*)d_in[4];
    const float* b2 = (const float*)d_in[5];
    const float* W3 = (const float*)d_in[6];
    const float* b3 = (const float*)d_in[7];
    float* out = (float*)d_out;

    fgen<<<28160, 256>>>(x, nb);
    wtrans<<<30976, 256>>>(W1, W2, W3);

    size_t smem = SMEM_FLOATS * sizeof(float);
    cudaFuncSetAttribute(moe_main, cudaFuncAttributeMaxDynamicSharedMemorySize, (int)smem);
    moe_main<<<dim3(88, MT_), 256, smem>>>(x, b1, b2, b3);

    moe_red_part<<<NB_RED, 256>>>();
    moe_red_final<<<1, 128>>>(out);
}